// round 5
// baseline (speedup 1.0000x reference)
#include <cuda_runtime.h>
#include <cuda_bf16.h>
#include <math.h>
#include <stdint.h>

// Problem dims (fixed by the dataset)
#define B_   512
#define T1_  64
#define E_   50
#define H_   32
#define N_   32768
#define T2_  32
#define DN_  49
#define FCIN_ 305

#define NP2  (N_ * T2_)        // 1048576 timeline (seq,t) pairs
#define PB2  (NP2 / 128)       // 8192 proj blocks for rnn2
#define NP1  (B_ * T1_)        // 32768 text (seq,t) pairs
#define PB1  (NP1 / 128)       // 256 proj blocks for rnn1

#define POS_INF_F (__int_as_float(0x7f800000))

typedef unsigned long long ull;

// Scratch (static device globals — no runtime allocation)
__device__ float g_P2[(size_t)2 * T2_ * N_ * H_];  // [dir][t][seq][32] 268MB
__device__ float g_P1[(size_t)2 * T1_ * B_ * H_];  // [dir][t][seq][32] 8.4MB
__device__ float g_h2[(size_t)N_ * 64];            // [N, 2H]
__device__ float g_hn[(size_t)B_ * 64];            // [B, 2H]
__device__ float g_red[(size_t)B_ * 192];          // [B, mean|min|max]

// ---------------- packed f32x2 helpers (Blackwell) ----------------
__device__ __forceinline__ ull ffma2(ull a, ull b, ull c) {
    ull d;
    asm("fma.rn.f32x2 %0, %1, %2, %3;" : "=l"(d) : "l"(a), "l"(b), "l"(c));
    return d;
}
__device__ __forceinline__ ull pack2(float x) {
    ull r; asm("mov.b64 %0, {%1, %1};" : "=l"(r) : "f"(x)); return r;
}
__device__ __forceinline__ void unpack2(ull v, float& lo, float& hi) {
    asm("mov.b64 {%0, %1}, %2;" : "=f"(lo), "=f"(hi) : "l"(v));
}

__device__ __forceinline__ float tanh_fast(float x) {
    float ax = fabsf(x);
    float e  = __expf(-2.0f * ax);
    float r  = __fdividef(1.0f - e, 1.0f + e);
    return copysignf(r, x);
}

// per-thread cp.async (16B); no cross-thread sharing -> no block sync needed
__device__ __forceinline__ void cp16(uint32_t saddr, const float* g) {
    asm volatile("cp.async.ca.shared.global [%0], [%1], 16;" :: "r"(saddr), "l"(g));
}
#define CP_COMMIT() asm volatile("cp.async.commit_group;")
#define CP_WAIT1()  asm volatile("cp.async.wait_group 1;")

// ---------------------------------------------------------------------------
// Projection kernel: P[dir][t][seq][i] = x[seq,t,:] @ W_ih^T + (b_ih + b_hh)
// One thread per (seq,t) pair, BOTH directions (shares x). f32x2 packed FMAs.
// blocks [0, PB2): rnn2/timeline;  [PB2, PB2+PB1): rnn1/text.
// ---------------------------------------------------------------------------
__global__ void __launch_bounds__(128) proj_kernel(
    const float* __restrict__ timeline, const float* __restrict__ text,
    const float* __restrict__ w2f, const float* __restrict__ b2if, const float* __restrict__ b2hf,
    const float* __restrict__ w2b, const float* __restrict__ b2ib, const float* __restrict__ b2hb,
    const float* __restrict__ w1f, const float* __restrict__ b1if, const float* __restrict__ b1hf,
    const float* __restrict__ w1b, const float* __restrict__ b1ib, const float* __restrict__ b1hb)
{
    __shared__ __align__(16) float sW[E_ * 64];    // [e][dir*32+i]
    __shared__ __align__(16) float sBias[64];      // [dir*32+i]
    __shared__ float sX[128 * 51];                 // pad 51: conflict-free reads

    const int tid = threadIdx.x;
    const int blk = blockIdx.x;

    const float* X; const float* wA; const float* wB;
    const float* bAi; const float* bAh; const float* bBi; const float* bBh;
    float* P; int NS, tsh; size_t pair0;

    if (blk < PB2) {
        X = timeline; pair0 = (size_t)blk * 128; NS = N_; tsh = 5; P = g_P2;
        wA = w2f; bAi = b2if; bAh = b2hf; wB = w2b; bBi = b2ib; bBh = b2hb;
    } else {
        X = text; pair0 = (size_t)(blk - PB2) * 128; NS = B_; tsh = 6; P = g_P1;
        wA = w1f; bAi = b1if; bAh = b1hf; wB = w1b; bBi = b1ib; bBh = b1hb;
    }

    // Stage weights transposed, both dirs: sW[e*64 + d*32 + i] = W_d[i][e]
    for (int idx = tid; idx < H_ * E_; idx += 128) {
        int i = idx / E_, e = idx - i * E_;
        sW[e * 64 + i]      = wA[idx];
        sW[e * 64 + 32 + i] = wB[idx];
    }
    if (tid < 32) {
        sBias[tid]      = bAi[tid] + bAh[tid];
        sBias[32 + tid] = bBi[tid] + bBh[tid];
    }
    // Stage x rows for this block's 128 pairs (contiguous in memory)
    {
        const float* src = X + pair0 * E_;
        for (int idx = tid; idx < 128 * E_; idx += 128)
            sX[(idx / E_) * 51 + (idx % E_)] = src[idx];
    }
    __syncthreads();

    ull acc[32];   // [0..15]=dir0 i-pairs, [16..31]=dir1
    {
        const longlong2* b2v = reinterpret_cast<const longlong2*>(sBias);
#pragma unroll
        for (int q = 0; q < 16; q++) {
            longlong2 v = b2v[q];
            acc[2*q]   = (ull)v.x;
            acc[2*q+1] = (ull)v.y;
        }
    }
    const float* xr = &sX[tid * 51];
    for (int e = 0; e < E_; e++) {
        ull xe2 = pack2(xr[e]);
        const longlong2* w = reinterpret_cast<const longlong2*>(&sW[e * 64]);
#pragma unroll
        for (int q = 0; q < 16; q++) {
            longlong2 v = w[q];
            acc[2*q]   = ffma2((ull)v.x, xe2, acc[2*q]);
            acc[2*q+1] = ffma2((ull)v.y, xe2, acc[2*q+1]);
        }
    }

    // Write P[dir][t][seq][0..31] (each thread writes 2 full 128B lines)
    const size_t pr = pair0 + tid;
    const int T   = 1 << tsh;
    const int seq = (int)(pr >> tsh);
    const int t   = (int)(pr & (T - 1));
#pragma unroll
    for (int d = 0; d < 2; d++) {
        float* o = P + (((size_t)d * T + t) * NS + seq) * 32;
        longlong2* ov = reinterpret_cast<longlong2*>(o);
#pragma unroll
        for (int q = 0; q < 8; q++) {
            longlong2 v;
            v.x = (long long)acc[d*16 + 2*q];
            v.y = (long long)acc[d*16 + 2*q + 1];
            ov[q] = v;
        }
    }
}

// ---------------------------------------------------------------------------
// Recurrence kernel: h_{t} = tanh(P[t] + h_{t-1} @ W_hh^T)
// blocks [0,512): rnn2 (dir = blk&1, 128 seqs each); [512,520): rnn1.
// P streamed via per-thread cp.async double-buffer (no block sync in loop).
// ---------------------------------------------------------------------------
__global__ void __launch_bounds__(128) rec_kernel(
    const float* __restrict__ r2_whf, const float* __restrict__ r2_whb,
    const float* __restrict__ r1_whf, const float* __restrict__ r1_whb)
{
    __shared__ __align__(16) float sWhh[H_ * H_];      // [j][i]
    __shared__ __align__(16) float sP[2][128 * 36];    // stride 36: cp.async 16B-aligned, conflict-free

    const int tid = threadIdx.x;
    const int blk = blockIdx.x;

    const float* whh; const float* P; float* dst;
    int T, NS, seq0, dir;

    if (blk < 512) {
        dir = blk & 1; const int grp = blk >> 1;
        T = T2_; NS = N_; seq0 = grp * 128; dst = g_h2;
        P = g_P2 + (size_t)dir * T2_ * N_ * 32;
        whh = dir ? r2_whb : r2_whf;
    } else {
        const int b1 = blk - 512; dir = b1 & 1; const int grp = b1 >> 1;
        T = T1_; NS = B_; seq0 = grp * 128; dst = g_hn;
        P = g_P1 + (size_t)dir * T1_ * B_ * 32;
        whh = dir ? r1_whb : r1_whf;
    }

    // Stage W_hh transposed: sWhh[j*32+i] = whh[i*32+j]
    for (int idx = tid; idx < H_ * H_; idx += 128) {
        int i = idx >> 5, j = idx & 31;
        sWhh[j * 32 + i] = whh[idx];
    }
    __syncthreads();

    // P traversal: fwd reads t=0..T-1, bwd reads t=T-1..0 (both sequential in
    // traversal order via signed pointer step).
    const float* p = P + (((size_t)(dir ? (T - 1) : 0)) * NS + (seq0 + tid)) * 32;
    const long long pstep = (dir ? -1LL : 1LL) * (long long)NS * 32;

    const uint32_t slot0 = (uint32_t)__cvta_generic_to_shared(&sP[0][tid * 36]);
    const uint32_t slot1 = (uint32_t)__cvta_generic_to_shared(&sP[1][tid * 36]);

    // Prefetch t=0 into buf0
#pragma unroll
    for (int q = 0; q < 8; q++) cp16(slot0 + q * 16, p + q * 4);
    CP_COMMIT();
    p += pstep;

    float h[H_];
#pragma unroll
    for (int i = 0; i < H_; i++) h[i] = 0.0f;

    for (int t = 0; t < T; t++) {
        const int buf = t & 1;
        // Prefetch next step into the other buffer
        if (t + 1 < T) {
            const uint32_t s = (buf ? slot0 : slot1);
#pragma unroll
            for (int q = 0; q < 8; q++) cp16(s + q * 16, p + q * 4);
            p += pstep;
        }
        CP_COMMIT();          // group committed every iter (possibly empty)
        CP_WAIT1();           // current step's data ready (own-thread only)

        ull acc[16];
        {
            const longlong2* ps = reinterpret_cast<const longlong2*>(&sP[buf][tid * 36]);
#pragma unroll
            for (int q = 0; q < 8; q++) {
                longlong2 v = ps[q];
                acc[2*q]   = (ull)v.x;
                acc[2*q+1] = (ull)v.y;
            }
        }
#pragma unroll
        for (int j = 0; j < H_; j++) {
            ull hj2 = pack2(h[j]);
            const longlong2* w = reinterpret_cast<const longlong2*>(&sWhh[j * 32]);
#pragma unroll
            for (int q = 0; q < 8; q++) {
                longlong2 v = w[q];
                acc[2*q]   = ffma2((ull)v.x, hj2, acc[2*q]);
                acc[2*q+1] = ffma2((ull)v.y, hj2, acc[2*q+1]);
            }
        }
#pragma unroll
        for (int q = 0; q < 16; q++) {
            float lo, hi;
            unpack2(acc[q], lo, hi);
            h[2*q]   = tanh_fast(lo);
            h[2*q+1] = tanh_fast(hi);
        }
    }

    float* o = dst + (size_t)(seq0 + tid) * 64 + dir * 32;
#pragma unroll
    for (int q = 0; q < 8; q++) {
        float4 v = make_float4(h[4*q], h[4*q+1], h[4*q+2], h[4*q+3]);
        reinterpret_cast<float4*>(o)[q] = v;
    }
}

// ---------------------------------------------------------------------------
// Ragged segment mean/min/max of g_h2 (defensively clamped).
// ---------------------------------------------------------------------------
__global__ void reduce_kernel(const int* __restrict__ te)
{
    const int b = blockIdx.x;
    const int f = threadIdx.x;

    long long start = 0;
    for (int k = 0; k < b; k++) start += te[k];
    if (start < 0) start = 0;
    if (start > N_) start = N_;
    int cnt = te[b];
    if (cnt < 1) cnt = 1;
    if (start + cnt > N_) cnt = (int)(N_ - start);
    if (cnt < 1) cnt = 1;

    const float* p = g_h2 + (size_t)start * 64 + f;
    float s = 0.0f, mn = POS_INF_F, mx = -POS_INF_F;
    for (int r = 0; r < cnt; r++) {
        float v = p[(size_t)r * 64];
        s += v; mn = fminf(mn, v); mx = fmaxf(mx, v);
    }
    float* o = g_red + (size_t)b * 192;
    o[f]       = s / (float)cnt;
    o[64 + f]  = mn;
    o[128 + f] = mx;
}

// ---------------------------------------------------------------------------
// fc1 (305->32) tanh, fc2 (32->1) sigmoid. One warp per batch row.
// ---------------------------------------------------------------------------
__global__ void fc_kernel(const float* __restrict__ normal,
                          const float* __restrict__ fc1_w,
                          const float* __restrict__ fc1_b,
                          const float* __restrict__ fc2_w,
                          const float* __restrict__ fc2_b,
                          float* __restrict__ out)
{
    const int b = blockIdx.x;
    const int i = threadIdx.x;
    __shared__ float x[FCIN_];

    for (int k = i; k < FCIN_; k += 32) {
        float v;
        if (k < 64)        v = g_hn[(size_t)b * 64 + k];
        else if (k < 113)  v = normal[(size_t)b * DN_ + (k - 64)];
        else               v = g_red[(size_t)b * 192 + (k - 113)];
        x[k] = v;
    }
    __syncwarp();

    float a = fc1_b[i];
    const float* w = fc1_w + (size_t)i * FCIN_;
    for (int k = 0; k < FCIN_; k++) a = fmaf(w[k], x[k], a);
    float y = tanh_fast(a);
    float z = y * fc2_w[i];
#pragma unroll
    for (int off = 16; off > 0; off >>= 1)
        z += __shfl_xor_sync(0xffffffffu, z, off);
    if (i == 0)
        out[b] = 1.0f / (1.0f + __expf(-(z + fc2_b[0])));
}

extern "C" void kernel_launch(void* const* d_in, const int* in_sizes, int n_in,
                              void* d_out, int out_size)
{
    // Resolve input ordering: dict order has timeline_elements (512 int32) at
    // index 3; signature order has it last.
    int wbase; const int* te;
    if (in_sizes[3] == B_) { wbase = 4;  te = (const int*)d_in[3]; }
    else                   { wbase = 3;  te = (const int*)d_in[n_in - 1]; }

    const float* normal   = (const float*)d_in[0];
    const float* text     = (const float*)d_in[1];
    const float* timeline = (const float*)d_in[2];

    const float* w[16];
    for (int k = 0; k < 16; k++) w[k] = (const float*)d_in[wbase + k];
    // w layout per setup: rnn1[wif,whf,bif,bhf, wib,whb,bib,bhb], then rnn2 same
    const float* fc1_w = (const float*)d_in[wbase + 16];
    const float* fc1_b = (const float*)d_in[wbase + 17];
    const float* fc2_w = (const float*)d_in[wbase + 18];
    const float* fc2_b = (const float*)d_in[wbase + 19];

    proj_kernel<<<PB2 + PB1, 128>>>(
        timeline, text,
        /* rnn2 fwd */ w[8],  w[10], w[11],
        /* rnn2 bwd */ w[12], w[14], w[15],
        /* rnn1 fwd */ w[0],  w[2],  w[3],
        /* rnn1 bwd */ w[4],  w[6],  w[7]);

    rec_kernel<<<520, 128>>>(w[9], w[13], w[1], w[5]);

    reduce_kernel<<<B_, 64>>>(te);

    fc_kernel<<<B_, 32>>>(normal, fc1_w, fc1_b, fc2_w, fc2_b, (float*)d_out);
}